// round 7
// baseline (speedup 1.0000x reference)
#include <cuda_runtime.h>
#include <cuda_fp16.h>
#include <cstdint>

#define NN   100000
#define CC   128
#define EMAX 1600000
#define NB   ((NN + 255) / 256)        // 391 scan blocks

// ---------------- scratch (static device globals) --------------------------
__device__ __align__(16) float  g_agg[(size_t)NN * CC];  // 51.2 MB fp32 agg
__device__ __align__(16) __half g_hx[(size_t)NN * CC];   // 25.6 MB half features
__device__ __align__(16) int2   g_edge[EMAX];            // 12.8 MB (src, w-bits)
__device__ int   g_cnt[NN];
__device__ int   g_rowstart[NN];
__device__ int   g_cursor[NN];
__device__ int   g_bsum[NB];
__device__ int   g_boff[NB];
__device__ double g_sum[2][CC];
__device__ double g_sumsq[2][CC];

// ---------------- CSR build + feat conversion ------------------------------
__global__ void __launch_bounds__(256) k_init()
{
    int i = blockIdx.x * 256 + threadIdx.x;
    if (i < NN) g_cnt[i] = 0;
    if (blockIdx.x == 0 && threadIdx.x < CC) {
        g_sum[0][threadIdx.x] = 0.0;  g_sumsq[0][threadIdx.x] = 0.0;
        g_sum[1][threadIdx.x] = 0.0;  g_sumsq[1][threadIdx.x] = 0.0;
    }
}

__global__ void __launch_bounds__(256) k_cvt(const float* __restrict__ feat)
{
    size_t i = (size_t)blockIdx.x * 256 + threadIdx.x;   // float4 index
    if (i < (size_t)NN * (CC / 4)) {
        float4 v = ((const float4*)feat)[i];
        __half2 h0 = __floats2half2_rn(v.x, v.y);
        __half2 h1 = __floats2half2_rn(v.z, v.w);
        uint2 p;
        p.x = *(unsigned*)&h0;
        p.y = *(unsigned*)&h1;
        ((uint2*)g_hx)[i] = p;
    }
}

__global__ void __launch_bounds__(256) k_hist(const int* __restrict__ dst, int E)
{
    int e = blockIdx.x * 256 + threadIdx.x;
    if (e < E) atomicAdd(&g_cnt[dst[e]], 1);
}

__global__ void __launch_bounds__(256) k_scan1()
{
    __shared__ int sm[256];
    int tid = threadIdx.x;
    int i = blockIdx.x * 256 + tid;
    int c = (i < NN) ? g_cnt[i] : 0;
    sm[tid] = c;
    __syncthreads();
    #pragma unroll
    for (int off = 1; off < 256; off <<= 1) {
        int v = (tid >= off) ? sm[tid - off] : 0;
        __syncthreads();
        sm[tid] += v;
        __syncthreads();
    }
    if (i < NN) g_rowstart[i] = sm[tid] - c;
    if (tid == 255) g_bsum[blockIdx.x] = sm[255];
}

__global__ void __launch_bounds__(512) k_scan2()
{
    __shared__ int sm[512];
    int tid = threadIdx.x;
    int v = (tid < NB) ? g_bsum[tid] : 0;
    sm[tid] = v;
    __syncthreads();
    #pragma unroll
    for (int off = 1; off < 512; off <<= 1) {
        int u = (tid >= off) ? sm[tid - off] : 0;
        __syncthreads();
        sm[tid] += u;
        __syncthreads();
    }
    if (tid < NB) g_boff[tid] = sm[tid] - v;
}

__global__ void __launch_bounds__(256) k_scan3()
{
    int i = blockIdx.x * 256 + threadIdx.x;
    if (i < NN) {
        int r = g_rowstart[i] + g_boff[blockIdx.x];
        g_rowstart[i] = r;
        g_cursor[i]   = r;
    }
}

__global__ void __launch_bounds__(256) k_fill(const int* __restrict__ src,
                                              const int* __restrict__ dst,
                                              const float* __restrict__ ew,
                                              int E)
{
    int e = blockIdx.x * 256 + threadIdx.x;
    if (e < E) {
        int slot = atomicAdd(&g_cursor[dst[e]], 1);
        g_edge[slot] = make_int2(src[e], __float_as_int(ew[e]));
    }
}

// ---------------- gather aggregation: warp per node, half source rows ------
// MLP=4 software pipeline: 4 edge records loaded up front, then 4 independent
// row loads in flight, then FMAs. Breaks the idx->row serial latency chain.
template<int AFF>
__global__ void __launch_bounds__(256) k_gather(int sel,
                                                const float* __restrict__ gamma,
                                                const float* __restrict__ beta)
{
    __shared__ float s_sc[CC], s_sh[CC];
    const int tid  = threadIdx.x;
    const int lane = tid & 31;

    if (AFF) {
        if (tid < CC) {
            double mean = g_sum[sel][tid]   * (1.0 / NN);
            double var  = g_sumsq[sel][tid] * (1.0 / NN) - mean * mean;
            float sc = gamma[tid] * rsqrtf((float)var + 1e-5f);
            s_sc[tid] = sc;
            s_sh[tid] = beta[tid] - (float)mean * sc;
        }
        __syncthreads();
    }

    int v = blockIdx.x * 8 + (tid >> 5);
    if (v >= NN) return;

    float4 sc4, sh4;
    if (AFF) {
        sc4 = *(const float4*)(s_sc + lane * 4);
        sh4 = *(const float4*)(s_sh + lane * 4);
    }

    const int start = g_rowstart[v];
    const int deg   = g_cnt[v];
    const int2* __restrict__ ep = g_edge + start;
    const __half* __restrict__ x = g_hx;
    const unsigned laneOff = lane * 4;

    float4 accA = make_float4(0.f, 0.f, 0.f, 0.f);
    float4 accB = make_float4(0.f, 0.f, 0.f, 0.f);

    int j = 0;
    for (; j + 4 <= deg; j += 4) {
        // batch 1: edge records (broadcast 8B loads, independent)
        int2 e0 = ep[j], e1 = ep[j + 1], e2 = ep[j + 2], e3 = ep[j + 3];
        // batch 2: 4 independent row loads in flight
        uint2 r0 = *(const uint2*)(x + (size_t)e0.x * CC + laneOff);
        uint2 r1 = *(const uint2*)(x + (size_t)e1.x * CC + laneOff);
        uint2 r2 = *(const uint2*)(x + (size_t)e2.x * CC + laneOff);
        uint2 r3 = *(const uint2*)(x + (size_t)e3.x * CC + laneOff);
        float w0 = __int_as_float(e0.y), w1 = __int_as_float(e1.y);
        float w2 = __int_as_float(e2.y), w3 = __int_as_float(e3.y);

        float2 a0 = __half22float2(*(__half2*)&r0.x), b0 = __half22float2(*(__half2*)&r0.y);
        float2 a1 = __half22float2(*(__half2*)&r1.x), b1 = __half22float2(*(__half2*)&r1.y);
        float2 a2 = __half22float2(*(__half2*)&r2.x), b2 = __half22float2(*(__half2*)&r2.y);
        float2 a3 = __half22float2(*(__half2*)&r3.x), b3 = __half22float2(*(__half2*)&r3.y);
        if (AFF) {
            a0.x = fmaxf(fmaf(a0.x, sc4.x, sh4.x), 0.f);  a0.y = fmaxf(fmaf(a0.y, sc4.y, sh4.y), 0.f);
            b0.x = fmaxf(fmaf(b0.x, sc4.z, sh4.z), 0.f);  b0.y = fmaxf(fmaf(b0.y, sc4.w, sh4.w), 0.f);
            a1.x = fmaxf(fmaf(a1.x, sc4.x, sh4.x), 0.f);  a1.y = fmaxf(fmaf(a1.y, sc4.y, sh4.y), 0.f);
            b1.x = fmaxf(fmaf(b1.x, sc4.z, sh4.z), 0.f);  b1.y = fmaxf(fmaf(b1.y, sc4.w, sh4.w), 0.f);
            a2.x = fmaxf(fmaf(a2.x, sc4.x, sh4.x), 0.f);  a2.y = fmaxf(fmaf(a2.y, sc4.y, sh4.y), 0.f);
            b2.x = fmaxf(fmaf(b2.x, sc4.z, sh4.z), 0.f);  b2.y = fmaxf(fmaf(b2.y, sc4.w, sh4.w), 0.f);
            a3.x = fmaxf(fmaf(a3.x, sc4.x, sh4.x), 0.f);  a3.y = fmaxf(fmaf(a3.y, sc4.y, sh4.y), 0.f);
            b3.x = fmaxf(fmaf(b3.x, sc4.z, sh4.z), 0.f);  b3.y = fmaxf(fmaf(b3.y, sc4.w, sh4.w), 0.f);
        }
        accA.x = fmaf(w0, a0.x, accA.x);  accA.y = fmaf(w0, a0.y, accA.y);
        accA.z = fmaf(w0, b0.x, accA.z);  accA.w = fmaf(w0, b0.y, accA.w);
        accB.x = fmaf(w1, a1.x, accB.x);  accB.y = fmaf(w1, a1.y, accB.y);
        accB.z = fmaf(w1, b1.x, accB.z);  accB.w = fmaf(w1, b1.y, accB.w);
        accA.x = fmaf(w2, a2.x, accA.x);  accA.y = fmaf(w2, a2.y, accA.y);
        accA.z = fmaf(w2, b2.x, accA.z);  accA.w = fmaf(w2, b2.y, accA.w);
        accB.x = fmaf(w3, a3.x, accB.x);  accB.y = fmaf(w3, a3.y, accB.y);
        accB.z = fmaf(w3, b3.x, accB.z);  accB.w = fmaf(w3, b3.y, accB.w);
    }
    for (; j < deg; j++) {
        int2 e0 = ep[j];
        uint2 r0 = *(const uint2*)(x + (size_t)e0.x * CC + laneOff);
        float w0 = __int_as_float(e0.y);
        float2 a0 = __half22float2(*(__half2*)&r0.x), b0 = __half22float2(*(__half2*)&r0.y);
        if (AFF) {
            a0.x = fmaxf(fmaf(a0.x, sc4.x, sh4.x), 0.f);  a0.y = fmaxf(fmaf(a0.y, sc4.y, sh4.y), 0.f);
            b0.x = fmaxf(fmaf(b0.x, sc4.z, sh4.z), 0.f);  b0.y = fmaxf(fmaf(b0.y, sc4.w, sh4.w), 0.f);
        }
        accA.x = fmaf(w0, a0.x, accA.x);  accA.y = fmaf(w0, a0.y, accA.y);
        accA.z = fmaf(w0, b0.x, accA.z);  accA.w = fmaf(w0, b0.y, accA.w);
    }
    accA.x += accB.x;  accA.y += accB.y;  accA.z += accB.z;  accA.w += accB.w;
    *(float4*)(g_agg + (size_t)v * CC + laneOff) = accA;
}

// ---------------- 128x128 GEMM (h = agg @ W) with fused BN stats -----------
#define SMEM_GEMM_FLOATS (16384 + 128 * 132 + 256)
__global__ void __launch_bounds__(256) k_gemm128(const float* __restrict__ Wg,
                                                 int sel)
{
    extern __shared__ float sm[];
    float* Ws   = sm;               // 128*128
    float* As   = sm + 16384;       // 128 * 132 (padded)
    float* csum = As + 128 * 132;   // 128
    float* csq  = csum + 128;       // 128

    const int tid = threadIdx.x;
    const int tx  = tid & 15;
    const int ty  = tid >> 4;
    const int rowBase = blockIdx.x * 128;

    {
        const float4* W4  = (const float4*)Wg;
        float4*       Ws4 = (float4*)Ws;
        #pragma unroll
        for (int i = 0; i < 16; i++) Ws4[i * 256 + tid] = W4[i * 256 + tid];
    }
    #pragma unroll
    for (int i = 0; i < 16; i++) {
        int fl  = i * 256 + tid;
        int row = fl >> 5;
        int k4  = fl & 31;
        int grow = rowBase + row;
        float4 v = make_float4(0.f, 0.f, 0.f, 0.f);
        if (grow < NN) v = ((const float4*)g_agg)[(size_t)grow * 32 + k4];
        *(float4*)(As + row * 132 + k4 * 4) = v;
    }
    if (tid < 128) { csum[tid] = 0.f; csq[tid] = 0.f; }
    __syncthreads();

    unsigned long long acc[8][4];
    #pragma unroll
    for (int r = 0; r < 8; r++)
        #pragma unroll
        for (int c = 0; c < 4; c++) acc[r][c] = 0ull;

    const int    colBase = tx * 8;
    const float* AsR     = As + (ty * 8) * 132;

    #pragma unroll 4
    for (int k = 0; k < 128; k++) {
        const ulonglong2* wp = (const ulonglong2*)(Ws + k * 128 + colBase);
        ulonglong2 p0 = wp[0];
        ulonglong2 p1 = wp[1];
        unsigned long long bb0 = p0.x, bb1 = p0.y, bb2 = p1.x, bb3 = p1.y;
        #pragma unroll
        for (int r = 0; r < 8; r++) {
            float a = AsR[r * 132 + k];
            unsigned long long aa;
            asm("mov.b64 %0, {%1, %1};" : "=l"(aa) : "f"(a));
            asm("fma.rn.f32x2 %0, %1, %2, %0;" : "+l"(acc[r][0]) : "l"(aa), "l"(bb0));
            asm("fma.rn.f32x2 %0, %1, %2, %0;" : "+l"(acc[r][1]) : "l"(aa), "l"(bb1));
            asm("fma.rn.f32x2 %0, %1, %2, %0;" : "+l"(acc[r][2]) : "l"(aa), "l"(bb2));
            asm("fma.rn.f32x2 %0, %1, %2, %0;" : "+l"(acc[r][3]) : "l"(aa), "l"(bb3));
        }
    }

    float psum[8], psq[8];
    #pragma unroll
    for (int jj = 0; jj < 8; jj++) { psum[jj] = 0.f; psq[jj] = 0.f; }

    #pragma unroll
    for (int r = 0; r < 8; r++) {
        int grow = rowBase + ty * 8 + r;
        float v[8];
        #pragma unroll
        for (int c = 0; c < 4; c++)
            asm("mov.b64 {%0, %1}, %2;"
                : "=f"(v[c * 2]), "=f"(v[c * 2 + 1]) : "l"(acc[r][c]));
        if (grow < NN) {
            __half2 h0 = __floats2half2_rn(v[0], v[1]);
            __half2 h1 = __floats2half2_rn(v[2], v[3]);
            __half2 h2 = __floats2half2_rn(v[4], v[5]);
            __half2 h3 = __floats2half2_rn(v[6], v[7]);
            uint4 p;
            p.x = *(unsigned*)&h0;  p.y = *(unsigned*)&h1;
            p.z = *(unsigned*)&h2;  p.w = *(unsigned*)&h3;
            *(uint4*)(g_hx + (size_t)grow * CC + colBase) = p;
            #pragma unroll
            for (int jj = 0; jj < 8; jj++) { psum[jj] += v[jj]; psq[jj] += v[jj] * v[jj]; }
        }
    }
    #pragma unroll
    for (int jj = 0; jj < 8; jj++) {
        atomicAdd(&csum[colBase + jj], psum[jj]);
        atomicAdd(&csq[colBase + jj],  psq[jj]);
    }
    __syncthreads();
    if (tid < 128) {
        atomicAdd(&g_sum[sel][tid],   (double)csum[tid]);
        atomicAdd(&g_sumsq[sel][tid], (double)csq[tid]);
    }
}

// ---------------- final GEMM 128 -> 40 with bias, writes d_out -------------
#define SMEM_OUT_FLOATS (5120 + 128 * 132)
__global__ void __launch_bounds__(256) k_gemm_out(const float* __restrict__ W3,
                                                  const float* __restrict__ b3,
                                                  float* __restrict__ out)
{
    extern __shared__ float sm[];
    float* Ws = sm;            // 128*40
    float* As = sm + 5120;     // 128*132

    const int tid = threadIdx.x;
    const int rowBase = blockIdx.x * 128;

    for (int i = tid; i < 5120; i += 256) Ws[i] = W3[i];
    #pragma unroll
    for (int i = 0; i < 16; i++) {
        int fl  = i * 256 + tid;
        int row = fl >> 5;
        int k4  = fl & 31;
        int grow = rowBase + row;
        float4 v = make_float4(0.f, 0.f, 0.f, 0.f);
        if (grow < NN) v = ((const float4*)g_agg)[(size_t)grow * 32 + k4];
        *(float4*)(As + row * 132 + k4 * 4) = v;
    }
    __syncthreads();

    const int cg = tid & 7;
    const int rg = tid >> 3;
    float acc[4][5];
    #pragma unroll
    for (int r = 0; r < 4; r++)
        #pragma unroll
        for (int j = 0; j < 5; j++) acc[r][j] = 0.f;

    #pragma unroll 2
    for (int k = 0; k < 128; k++) {
        float b[5];
        #pragma unroll
        for (int j = 0; j < 5; j++) b[j] = Ws[k * 40 + cg * 5 + j];
        #pragma unroll
        for (int r = 0; r < 4; r++) {
            float a = As[(rg * 4 + r) * 132 + k];
            #pragma unroll
            for (int j = 0; j < 5; j++) acc[r][j] = fmaf(a, b[j], acc[r][j]);
        }
    }
    #pragma unroll
    for (int r = 0; r < 4; r++) {
        int grow = rowBase + rg * 4 + r;
        if (grow < NN) {
            #pragma unroll
            for (int j = 0; j < 5; j++)
                out[(size_t)grow * 40 + cg * 5 + j] = acc[r][j] + b3[cg * 5 + j];
        }
    }
}

// ---------------- launch ---------------------------------------------------
extern "C" void kernel_launch(void* const* d_in, const int* in_sizes, int n_in,
                              void* d_out, int out_size)
{
    const float* feat   = (const float*)d_in[0];
    const int*   src    = (const int*)  d_in[1];
    const int*   dst    = (const int*)  d_in[2];
    const float* ew     = (const float*)d_in[3];
    const float* W1     = (const float*)d_in[4];
    const float* W2     = (const float*)d_in[5];
    const float* W3     = (const float*)d_in[6];
    const float* b3     = (const float*)d_in[7];
    const float* gamma1 = (const float*)d_in[8];
    const float* beta1  = (const float*)d_in[9];
    const float* gamma2 = (const float*)d_in[10];
    const float* beta2  = (const float*)d_in[11];
    float* out = (float*)d_out;
    const int E = in_sizes[1];

    const int smemGemm = SMEM_GEMM_FLOATS * 4;
    const int smemOut  = SMEM_OUT_FLOATS  * 4;
    cudaFuncSetAttribute(k_gemm128,  cudaFuncAttributeMaxDynamicSharedMemorySize, smemGemm);
    cudaFuncSetAttribute(k_gemm_out, cudaFuncAttributeMaxDynamicSharedMemorySize, smemOut);

    const int egrid = (E + 255) / 256;
    const int ggrid = (NN + 127) / 128;
    const int agrid = (NN + 7) / 8;
    const int cgrid = (NN * (CC / 4) + 255) / 256;

    // ---- build CSR + convert feat to half (shared by all 3 layers) ----
    k_init <<<NB, 256>>>();
    k_cvt  <<<cgrid, 256>>>(feat);
    k_hist <<<egrid, 256>>>(dst, E);
    k_scan1<<<NB, 256>>>();
    k_scan2<<<1, 512>>>();
    k_scan3<<<NB, 256>>>();
    k_fill <<<egrid, 256>>>(src, dst, ew, E);

    // ---- layer 1 (gather from half feat) ----
    k_gather<0><<<agrid, 256>>>(0, nullptr, nullptr);
    k_gemm128<<<ggrid, 256, smemGemm>>>(W1, 0);

    // ---- layer 2 (gather from half h; BN1+ReLU fused) ----
    k_gather<1><<<agrid, 256>>>(0, gamma1, beta1);
    k_gemm128<<<ggrid, 256, smemGemm>>>(W2, 1);

    // ---- layer 3 (gather from half h; BN2+ReLU fused) ----
    k_gather<1><<<agrid, 256>>>(1, gamma2, beta2);
    k_gemm_out<<<ggrid, 256, smemOut>>>(W3, b3, out);
}

// round 8
// speedup vs baseline: 1.1477x; 1.1477x over previous
#include <cuda_runtime.h>
#include <cuda_fp16.h>
#include <cstdint>

#define NN   100000
#define CC   128
#define EMAX 1600000
#define NB   ((NN + 255) / 256)        // 391 scan blocks

// ---------------- scratch (static device globals) --------------------------
__device__ __align__(16) float  g_agg[(size_t)NN * CC];  // fp32 agg / z buffer
__device__ __align__(16) __half g_hx[(size_t)NN * CC];   // half features
__device__ int   g_cnt[NN];
__device__ int   g_rowstart[NN];
__device__ int   g_cursor[NN];
__device__ int   g_bsum[NB];
__device__ int   g_boff[NB];
__device__ int   g_psrc[EMAX];
__device__ float g_pw[EMAX];
__device__ double g_sum[2][CC];
__device__ double g_sumsq[2][CC];

// ---------------- CSR build + feat conversion ------------------------------
__global__ void __launch_bounds__(256) k_init()
{
    int i = blockIdx.x * 256 + threadIdx.x;
    if (i < NN) g_cnt[i] = 0;
    if (blockIdx.x == 0 && threadIdx.x < CC) {
        g_sum[0][threadIdx.x] = 0.0;  g_sumsq[0][threadIdx.x] = 0.0;
        g_sum[1][threadIdx.x] = 0.0;  g_sumsq[1][threadIdx.x] = 0.0;
    }
}

__global__ void __launch_bounds__(256) k_cvt(const float* __restrict__ feat)
{
    size_t i = (size_t)blockIdx.x * 256 + threadIdx.x;   // float4 index
    if (i < (size_t)NN * (CC / 4)) {
        float4 v = ((const float4*)feat)[i];
        __half2 h0 = __floats2half2_rn(v.x, v.y);
        __half2 h1 = __floats2half2_rn(v.z, v.w);
        uint2 p;
        p.x = *(unsigned*)&h0;
        p.y = *(unsigned*)&h1;
        ((uint2*)g_hx)[i] = p;
    }
}

__global__ void __launch_bounds__(256) k_hist(const int* __restrict__ dst, int E)
{
    int e = blockIdx.x * 256 + threadIdx.x;
    if (e < E) atomicAdd(&g_cnt[dst[e]], 1);
}

__global__ void __launch_bounds__(256) k_scan1()
{
    __shared__ int sm[256];
    int tid = threadIdx.x;
    int i = blockIdx.x * 256 + tid;
    int c = (i < NN) ? g_cnt[i] : 0;
    sm[tid] = c;
    __syncthreads();
    #pragma unroll
    for (int off = 1; off < 256; off <<= 1) {
        int v = (tid >= off) ? sm[tid - off] : 0;
        __syncthreads();
        sm[tid] += v;
        __syncthreads();
    }
    if (i < NN) g_rowstart[i] = sm[tid] - c;
    if (tid == 255) g_bsum[blockIdx.x] = sm[255];
}

__global__ void __launch_bounds__(512) k_scan2()
{
    __shared__ int sm[512];
    int tid = threadIdx.x;
    int v = (tid < NB) ? g_bsum[tid] : 0;
    sm[tid] = v;
    __syncthreads();
    #pragma unroll
    for (int off = 1; off < 512; off <<= 1) {
        int u = (tid >= off) ? sm[tid - off] : 0;
        __syncthreads();
        sm[tid] += u;
        __syncthreads();
    }
    if (tid < NB) g_boff[tid] = sm[tid] - v;
}

__global__ void __launch_bounds__(256) k_scan3()
{
    int i = blockIdx.x * 256 + threadIdx.x;
    if (i < NN) {
        int r = g_rowstart[i] + g_boff[blockIdx.x];
        g_rowstart[i] = r;
        g_cursor[i]   = r;
    }
}

__global__ void __launch_bounds__(256) k_fill(const int* __restrict__ src,
                                              const int* __restrict__ dst,
                                              const float* __restrict__ ew,
                                              int E)
{
    int e = blockIdx.x * 256 + threadIdx.x;
    if (e < E) {
        int slot = atomicAdd(&g_cursor[dst[e]], 1);
        g_psrc[slot] = src[e];
        g_pw[slot]   = ew[e];
    }
}

// ---------------- gather aggregation (layers 1-2): warp per node -----------
// Round-6 simple loop (fastest measured form — batching regressed).
template<int AFF>
__global__ void __launch_bounds__(256) k_gather(int sel,
                                                const float* __restrict__ gamma,
                                                const float* __restrict__ beta)
{
    __shared__ float s_sc[CC], s_sh[CC];
    const int tid  = threadIdx.x;
    const int lane = tid & 31;

    if (AFF) {
        if (tid < CC) {
            double mean = g_sum[sel][tid]   * (1.0 / NN);
            double var  = g_sumsq[sel][tid] * (1.0 / NN) - mean * mean;
            float sc = gamma[tid] * rsqrtf((float)var + 1e-5f);
            s_sc[tid] = sc;
            s_sh[tid] = beta[tid] - (float)mean * sc;
        }
        __syncthreads();
    }

    int v = blockIdx.x * 8 + (tid >> 5);
    if (v >= NN) return;

    float4 sc4, sh4;
    if (AFF) {
        sc4 = *(const float4*)(s_sc + lane * 4);
        sh4 = *(const float4*)(s_sh + lane * 4);
    }

    const int start = g_rowstart[v];
    const int deg   = g_cnt[v];
    float4 acc = make_float4(0.f, 0.f, 0.f, 0.f);
    const __half* __restrict__ x = g_hx;

    for (int j = 0; j < deg; j++) {
        int   s0 = g_psrc[start + j];
        float w0 = g_pw[start + j];
        uint2 raw = *(const uint2*)(x + (size_t)s0 * CC + lane * 4);
        float2 f0 = __half22float2(*(__half2*)&raw.x);
        float2 f1 = __half22float2(*(__half2*)&raw.y);
        if (AFF) {
            f0.x = fmaxf(fmaf(f0.x, sc4.x, sh4.x), 0.f);
            f0.y = fmaxf(fmaf(f0.y, sc4.y, sh4.y), 0.f);
            f1.x = fmaxf(fmaf(f1.x, sc4.z, sh4.z), 0.f);
            f1.y = fmaxf(fmaf(f1.y, sc4.w, sh4.w), 0.f);
        }
        acc.x = fmaf(w0, f0.x, acc.x);
        acc.y = fmaf(w0, f0.y, acc.y);
        acc.z = fmaf(w0, f1.x, acc.z);
        acc.w = fmaf(w0, f1.y, acc.w);
    }
    *(float4*)(g_agg + (size_t)v * CC + lane * 4) = acc;
}

// ---------------- 128x128 GEMM (h = agg @ W) with fused BN stats -----------
#define SMEM_GEMM_FLOATS (16384 + 128 * 132 + 256)
__global__ void __launch_bounds__(256) k_gemm128(const float* __restrict__ Wg,
                                                 int sel)
{
    extern __shared__ float sm[];
    float* Ws   = sm;               // 128*128
    float* As   = sm + 16384;       // 128 * 132 (padded)
    float* csum = As + 128 * 132;   // 128
    float* csq  = csum + 128;       // 128

    const int tid = threadIdx.x;
    const int tx  = tid & 15;
    const int ty  = tid >> 4;
    const int rowBase = blockIdx.x * 128;

    {
        const float4* W4  = (const float4*)Wg;
        float4*       Ws4 = (float4*)Ws;
        #pragma unroll
        for (int i = 0; i < 16; i++) Ws4[i * 256 + tid] = W4[i * 256 + tid];
    }
    #pragma unroll
    for (int i = 0; i < 16; i++) {
        int fl  = i * 256 + tid;
        int row = fl >> 5;
        int k4  = fl & 31;
        int grow = rowBase + row;
        float4 v = make_float4(0.f, 0.f, 0.f, 0.f);
        if (grow < NN) v = ((const float4*)g_agg)[(size_t)grow * 32 + k4];
        *(float4*)(As + row * 132 + k4 * 4) = v;
    }
    if (tid < 128) { csum[tid] = 0.f; csq[tid] = 0.f; }
    __syncthreads();

    unsigned long long acc[8][4];
    #pragma unroll
    for (int r = 0; r < 8; r++)
        #pragma unroll
        for (int c = 0; c < 4; c++) acc[r][c] = 0ull;

    const int    colBase = tx * 8;
    const float* AsR     = As + (ty * 8) * 132;

    #pragma unroll 4
    for (int k = 0; k < 128; k++) {
        const ulonglong2* wp = (const ulonglong2*)(Ws + k * 128 + colBase);
        ulonglong2 p0 = wp[0];
        ulonglong2 p1 = wp[1];
        unsigned long long bb0 = p0.x, bb1 = p0.y, bb2 = p1.x, bb3 = p1.y;
        #pragma unroll
        for (int r = 0; r < 8; r++) {
            float a = AsR[r * 132 + k];
            unsigned long long aa;
            asm("mov.b64 %0, {%1, %1};" : "=l"(aa) : "f"(a));
            asm("fma.rn.f32x2 %0, %1, %2, %0;" : "+l"(acc[r][0]) : "l"(aa), "l"(bb0));
            asm("fma.rn.f32x2 %0, %1, %2, %0;" : "+l"(acc[r][1]) : "l"(aa), "l"(bb1));
            asm("fma.rn.f32x2 %0, %1, %2, %0;" : "+l"(acc[r][2]) : "l"(aa), "l"(bb2));
            asm("fma.rn.f32x2 %0, %1, %2, %0;" : "+l"(acc[r][3]) : "l"(aa), "l"(bb3));
        }
    }

    float psum[8], psq[8];
    #pragma unroll
    for (int jj = 0; jj < 8; jj++) { psum[jj] = 0.f; psq[jj] = 0.f; }

    #pragma unroll
    for (int r = 0; r < 8; r++) {
        int grow = rowBase + ty * 8 + r;
        float v[8];
        #pragma unroll
        for (int c = 0; c < 4; c++)
            asm("mov.b64 {%0, %1}, %2;"
                : "=f"(v[c * 2]), "=f"(v[c * 2 + 1]) : "l"(acc[r][c]));
        if (grow < NN) {
            __half2 h0 = __floats2half2_rn(v[0], v[1]);
            __half2 h1 = __floats2half2_rn(v[2], v[3]);
            __half2 h2 = __floats2half2_rn(v[4], v[5]);
            __half2 h3 = __floats2half2_rn(v[6], v[7]);
            uint4 p;
            p.x = *(unsigned*)&h0;  p.y = *(unsigned*)&h1;
            p.z = *(unsigned*)&h2;  p.w = *(unsigned*)&h3;
            *(uint4*)(g_hx + (size_t)grow * CC + colBase) = p;
            #pragma unroll
            for (int jj = 0; jj < 8; jj++) { psum[jj] += v[jj]; psq[jj] += v[jj] * v[jj]; }
        }
    }
    #pragma unroll
    for (int jj = 0; jj < 8; jj++) {
        atomicAdd(&csum[colBase + jj], psum[jj]);
        atomicAdd(&csq[colBase + jj],  psq[jj]);
    }
    __syncthreads();
    if (tid < 128) {
        atomicAdd(&g_sum[sel][tid],   (double)csum[tid]);
        atomicAdd(&g_sumsq[sel][tid], (double)csq[tid]);
    }
}

// ---------------- layer-3 pre-transform: z = relu(bn2(h)) @ W3 -------------
// Reads half h rows, applies BN affine + ReLU, 128->40 GEMM, writes z (fp32)
// into g_agg (reused as z[N][40]).
#define SMEM_PRE_FLOATS (5120 + 128 * 132 + 256)
__global__ void __launch_bounds__(256) k_pre(const float* __restrict__ W3,
                                             const float* __restrict__ gamma,
                                             const float* __restrict__ beta)
{
    extern __shared__ float sm[];
    float* Ws   = sm;                 // 128*40
    float* As   = sm + 5120;          // 128*132
    float* s_sc = As + 128 * 132;     // 128
    float* s_sh = s_sc + 128;         // 128

    const int tid = threadIdx.x;
    const int rowBase = blockIdx.x * 128;

    if (tid < CC) {
        double mean = g_sum[1][tid]   * (1.0 / NN);
        double var  = g_sumsq[1][tid] * (1.0 / NN) - mean * mean;
        float sc = gamma[tid] * rsqrtf((float)var + 1e-5f);
        s_sc[tid] = sc;
        s_sh[tid] = beta[tid] - (float)mean * sc;
    }
    for (int i = tid; i < 5120; i += 256) Ws[i] = W3[i];
    __syncthreads();

    #pragma unroll
    for (int i = 0; i < 16; i++) {
        int fl  = i * 256 + tid;       // uint2 index within tile
        int row = fl >> 5;
        int q   = fl & 31;             // 4-channel group
        int grow = rowBase + row;
        float f[4] = {0.f, 0.f, 0.f, 0.f};
        if (grow < NN) {
            uint2 raw = *(const uint2*)(g_hx + (size_t)grow * CC + q * 4);
            float2 a = __half22float2(*(__half2*)&raw.x);
            float2 b = __half22float2(*(__half2*)&raw.y);
            f[0] = fmaxf(fmaf(a.x, s_sc[q * 4 + 0], s_sh[q * 4 + 0]), 0.f);
            f[1] = fmaxf(fmaf(a.y, s_sc[q * 4 + 1], s_sh[q * 4 + 1]), 0.f);
            f[2] = fmaxf(fmaf(b.x, s_sc[q * 4 + 2], s_sh[q * 4 + 2]), 0.f);
            f[3] = fmaxf(fmaf(b.y, s_sc[q * 4 + 3], s_sh[q * 4 + 3]), 0.f);
        }
        *(float4*)(As + row * 132 + q * 4) = make_float4(f[0], f[1], f[2], f[3]);
    }
    __syncthreads();

    const int cg = tid & 7;    // 8 col groups x 5 cols
    const int rg = tid >> 3;   // 32 row groups x 4 rows
    float acc[4][5];
    #pragma unroll
    for (int r = 0; r < 4; r++)
        #pragma unroll
        for (int j = 0; j < 5; j++) acc[r][j] = 0.f;

    #pragma unroll 2
    for (int k = 0; k < 128; k++) {
        float b[5];
        #pragma unroll
        for (int j = 0; j < 5; j++) b[j] = Ws[k * 40 + cg * 5 + j];
        #pragma unroll
        for (int r = 0; r < 4; r++) {
            float a = As[(rg * 4 + r) * 132 + k];
            #pragma unroll
            for (int j = 0; j < 5; j++) acc[r][j] = fmaf(a, b[j], acc[r][j]);
        }
    }
    float* __restrict__ z = g_agg;    // reuse as z[N][40]
    #pragma unroll
    for (int r = 0; r < 4; r++) {
        int grow = rowBase + rg * 4 + r;
        if (grow < NN) {
            #pragma unroll
            for (int j = 0; j < 5; j++)
                z[(size_t)grow * 40 + cg * 5 + j] = acc[r][j];
        }
    }
}

// ---------------- layer-3 aggregation over 40 channels, + bias, -> out -----
// Warp per node; lanes 0..19 each own 2 channels (float2 = 8B, 160B/row).
__global__ void __launch_bounds__(256) k_gather_out(const float* __restrict__ b3,
                                                    float* __restrict__ out)
{
    int v = blockIdx.x * 8 + (threadIdx.x >> 5);
    if (v >= NN) return;
    const int lane = threadIdx.x & 31;

    const int start = g_rowstart[v];
    const int deg   = g_cnt[v];
    const float* __restrict__ z = g_agg;

    float2 acc = make_float2(0.f, 0.f);
    for (int j = 0; j < deg; j++) {
        int   s0 = g_psrc[start + j];
        float w0 = g_pw[start + j];
        if (lane < 20) {
            float2 zz = *(const float2*)(z + (size_t)s0 * 40 + lane * 2);
            acc.x = fmaf(w0, zz.x, acc.x);
            acc.y = fmaf(w0, zz.y, acc.y);
        }
    }
    if (lane < 20) {
        float2 bb = *(const float2*)(b3 + lane * 2);
        float2 o;
        o.x = acc.x + bb.x;
        o.y = acc.y + bb.y;
        *(float2*)(out + (size_t)v * 40 + lane * 2) = o;
    }
}

// ---------------- launch ---------------------------------------------------
extern "C" void kernel_launch(void* const* d_in, const int* in_sizes, int n_in,
                              void* d_out, int out_size)
{
    const float* feat   = (const float*)d_in[0];
    const int*   src    = (const int*)  d_in[1];
    const int*   dst    = (const int*)  d_in[2];
    const float* ew     = (const float*)d_in[3];
    const float* W1     = (const float*)d_in[4];
    const float* W2     = (const float*)d_in[5];
    const float* W3     = (const float*)d_in[6];
    const float* b3     = (const float*)d_in[7];
    const float* gamma1 = (const float*)d_in[8];
    const float* beta1  = (const float*)d_in[9];
    const float* gamma2 = (const float*)d_in[10];
    const float* beta2  = (const float*)d_in[11];
    float* out = (float*)d_out;
    const int E = in_sizes[1];

    const int smemGemm = SMEM_GEMM_FLOATS * 4;
    const int smemPre  = SMEM_PRE_FLOATS  * 4;
    cudaFuncSetAttribute(k_gemm128, cudaFuncAttributeMaxDynamicSharedMemorySize, smemGemm);
    cudaFuncSetAttribute(k_pre,     cudaFuncAttributeMaxDynamicSharedMemorySize, smemPre);

    const int egrid = (E + 255) / 256;
    const int ggrid = (NN + 127) / 128;
    const int agrid = (NN + 7) / 8;
    const int cgrid = (NN * (CC / 4) + 255) / 256;

    // ---- build CSR + convert feat to half (shared by all 3 layers) ----
    k_init <<<NB, 256>>>();
    k_cvt  <<<cgrid, 256>>>(feat);
    k_hist <<<egrid, 256>>>(dst, E);
    k_scan1<<<NB, 256>>>();
    k_scan2<<<1, 512>>>();
    k_scan3<<<NB, 256>>>();
    k_fill <<<egrid, 256>>>(src, dst, ew, E);

    // ---- layer 1 ----
    k_gather<0><<<agrid, 256>>>(0, nullptr, nullptr);
    k_gemm128<<<ggrid, 256, smemGemm>>>(W1, 0);

    // ---- layer 2 (BN1+ReLU fused into gather) ----
    k_gather<1><<<agrid, 256>>>(0, gamma1, beta1);
    k_gemm128<<<ggrid, 256, smemGemm>>>(W2, 1);

    // ---- layer 3: pre-transform (BN2+ReLU+W3), then 40-ch aggregation ----
    k_pre<<<ggrid, 256, smemPre>>>(W3, gamma2, beta2);
    k_gather_out<<<agrid, 256>>>(b3, out);
}